// round 2
// baseline (speedup 1.0000x reference)
#include <cuda_runtime.h>
#include <cuda_bf16.h>
#include <cstdint>

// Problem constants
#define NB   16
#define NPTS 65536
#define NPAT 64      // NUM_PATCHES
#define KNN  32      // PATCH_SIZE

// FPS decomposition: 8 blocks per batch, 1024 threads, 8 points per thread
#define FPS_BLKS   8
#define FPS_THR    1024
#define FPS_PPT    8           // points per thread = NPTS / (FPS_BLKS*FPS_THR)

// Scratch (allocation-free rule: __device__ globals)
__device__ float4             g_pts4[NB * NPTS];          // x,y,z,|p|^2 (FMA-chain p2)
__device__ unsigned long long g_part[NB * NPAT * FPS_BLKS]; // per-iter per-block argmax slot
__device__ unsigned int       g_rel [NB * NPAT];            // per-iter release word (idx+1)

// ---------------------------------------------------------------------------
// Kernel 0: prep — pad points to float4 with p2, zero barrier state (every replay)
// p2 uses the XLA/LLVM FP-contraction shape: fma(z,z, fma(y,y, x*x))
// ---------------------------------------------------------------------------
__global__ void prep_kernel(const float* __restrict__ pts) {
    int i = blockIdx.x * blockDim.x + threadIdx.x;
    if (i < NB * NPAT * FPS_BLKS) g_part[i] = 0ull;
    if (i < NB * NPAT)            g_rel[i]  = 0u;
    int total = NB * NPTS;
    for (int p = i; p < total; p += gridDim.x * blockDim.x) {
        float x = pts[3 * p + 0];
        float y = pts[3 * p + 1];
        float z = pts[3 * p + 2];
        float p2 = __fmaf_rn(z, z, __fmaf_rn(y, y, __fmul_rn(x, x)));
        g_pts4[p] = make_float4(x, y, z, p2);
    }
}

// ---------------------------------------------------------------------------
// Kernel 1: FPS — 8 cooperating blocks per batch, points+min_d in registers,
// lock-free L2 barrier per iteration (slots pre-zeroed by prep each replay).
// Arithmetic UNCHANGED from round 1 (evidence says it matches the reference).
// ---------------------------------------------------------------------------
__global__ void __launch_bounds__(FPS_THR, 1)
fps_kernel(float* __restrict__ centers_out /* [NB][NPAT][3] */) {
    const int b    = blockIdx.y;
    const int sub  = blockIdx.x;          // 0..7
    const int tid  = threadIdx.x;
    const int lane = tid & 31;
    const int wid  = tid >> 5;            // 0..31

    const float4* pts = g_pts4 + (size_t)b * NPTS;
    const int gbase = sub * (NPTS / FPS_BLKS);   // 8192 per sub-block

    float px[FPS_PPT], py[FPS_PPT], pz[FPS_PPT], md[FPS_PPT];
#pragma unroll
    for (int j = 0; j < FPS_PPT; j++) {
        float4 p = pts[gbase + j * FPS_THR + tid];
        px[j] = p.x; py[j] = p.y; pz[j] = p.z;
        md[j] = 3.402823466e38f;   // finfo(float32).max
    }

    __shared__ float sc[3];
    __shared__ unsigned long long wb[32];
    __shared__ int s_last;

    volatile unsigned long long* part = (volatile unsigned long long*)(g_part + (size_t)b * NPAT * FPS_BLKS);
    volatile unsigned int*       rel  = (volatile unsigned int*)(g_rel + (size_t)b * NPAT);

    int last = 0;
    for (int iter = 0; iter < NPAT; iter++) {
        if (tid == 0) {
            float4 c = pts[last];
            sc[0] = c.x; sc[1] = c.y; sc[2] = c.z;
            if (sub == 0) {
                centers_out[(b * NPAT + iter) * 3 + 0] = c.x;
                centers_out[(b * NPAT + iter) * 3 + 1] = c.y;
                centers_out[(b * NPAT + iter) * 3 + 2] = c.z;
            }
        }
        __syncthreads();
        float cx = sc[0], cy = sc[1], cz = sc[2];

        unsigned long long best = 0ull;
#pragma unroll
        for (int j = 0; j < FPS_PPT; j++) {
            float dx = px[j] - cx, dy = py[j] - cy, dz = pz[j] - cz;
            float d = __fadd_rn(__fadd_rn(__fmul_rn(dx, dx), __fmul_rn(dy, dy)), __fmul_rn(dz, dz));
            float m = fminf(md[j], d);
            md[j] = m;
            unsigned int gi = (unsigned int)(gbase + j * FPS_THR + tid);
            // max on (value, ~idx): ties -> lowest index (jnp.argmax picks first)
            unsigned long long key = ((unsigned long long)__float_as_uint(m) << 32) | (unsigned int)(~gi);
            if (key > best) best = key;
        }
#pragma unroll
        for (int off = 16; off; off >>= 1) {
            unsigned long long o = __shfl_xor_sync(0xffffffffu, best, off);
            if (o > best) best = o;
        }
        if (lane == 0) wb[wid] = best;
        __syncthreads();
        if (wid == 0) {
            unsigned long long v = wb[lane];
#pragma unroll
            for (int off = 16; off; off >>= 1) {
                unsigned long long o = __shfl_xor_sync(0xffffffffu, v, off);
                if (o > v) v = o;
            }
            if (lane == 0) {
                part[iter * FPS_BLKS + sub] = v;   // nonzero (low word = ~idx != 0)
                if (sub == 0) {
                    unsigned long long m = 0ull;
                    for (int k = 0; k < FPS_BLKS; k++) {
                        unsigned long long s;
                        while ((s = part[iter * FPS_BLKS + k]) == 0ull) { __nanosleep(40); }
                        if (s > m) m = s;
                    }
                    unsigned int bi = ~(unsigned int)m;   // winning global index
                    rel[iter] = bi + 1u;                   // release (payload itself)
                }
            }
        }
        if (iter < NPAT - 1) {
            if (tid == 0) {
                unsigned int r;
                while ((r = rel[iter]) == 0u) { __nanosleep(40); }
                s_last = (int)(r - 1u);
            }
            __syncthreads();
            last = s_last;
        }
    }
}

// ---------------------------------------------------------------------------
// Kernel 2: exact KNN top-32 (sorted, stable) + gather + center subtraction.
// d2 arithmetic now matches XLA's lowering:
//   dot = fma(z,cz, fma(y,cy, x*cx))          (cuBLAS K-loop FMA chain)
//   c2  = fma(cz,cz, fma(cy,cy, cx*cx))       (LLVM contraction in fusion)
//   d2  = fma(-2, dot, c2 + p2)               (sub(add, mul) contracted)
// ---------------------------------------------------------------------------
__device__ __forceinline__ unsigned long long bsort32(unsigned long long v, int lane) {
#pragma unroll
    for (int k = 2; k <= 32; k <<= 1) {
#pragma unroll
        for (int j = k >> 1; j > 0; j >>= 1) {
            unsigned long long o = __shfl_xor_sync(0xffffffffu, v, j);
            bool up      = ((lane & k) == 0);
            bool keepmin = (((lane & j) == 0) == up);
            bool smaller = (v < o);
            v = (smaller == keepmin) ? v : o;
        }
    }
    return v;   // ascending across lanes
}

__device__ __forceinline__ unsigned long long bmerge32(unsigned long long v, int lane) {
#pragma unroll
    for (int j = 16; j > 0; j >>= 1) {
        unsigned long long o = __shfl_xor_sync(0xffffffffu, v, j);
        bool keepmin = ((lane & j) == 0);
        bool smaller = (v < o);
        v = (smaller == keepmin) ? v : o;
    }
    return v;   // sorts a bitonic sequence ascending
}

#define KNN_CH 1024   // points per half-chunk staged in smem

__global__ void __launch_bounds__(512, 1)
knn_kernel(const float* __restrict__ centers /* [NB][NPAT][3] */,
           float* __restrict__ patches_out   /* [NB][NPAT][KNN][3] */) {
    const int b    = blockIdx.y;      // 16
    const int grp  = blockIdx.x;      // 8 -> centers grp*8 .. grp*8+7
    const int tid  = threadIdx.x;
    const int lane = tid & 31;
    const int w    = tid >> 5;        // 0..15
    const int cl   = w & 7;
    const int half = w >> 3;          // 0/1
    const int c    = grp * 8 + cl;

    const float4* pbase = g_pts4 + (size_t)b * NPTS;

    const float cx = centers[(b * NPAT + c) * 3 + 0];
    const float cy = centers[(b * NPAT + c) * 3 + 1];
    const float cz = centers[(b * NPAT + c) * 3 + 2];
    const float c2 = __fmaf_rn(cz, cz, __fmaf_rn(cy, cy, __fmul_rn(cx, cx)));

    unsigned long long L = 0xFF80000000000000ull;   // key for d2=+inf, idx 0
    float curMax = __int_as_float(0x7f800000);      // +inf

    __shared__ float4 chunk[2 * KNN_CH];            // 32 KB
    __shared__ unsigned long long smg[8][32];       // 2 KB (half-merge)

    const int hbase = half * (NPTS / 2);

    for (int cb = 0; cb < NPTS / 2; cb += KNN_CH) {
        __syncthreads();   // previous chunk fully consumed before overwrite
        for (int t = tid; t < 2 * KNN_CH; t += 512) {
            int hh = t >> 10;           // which half
            int off = t & (KNN_CH - 1);
            chunk[t] = pbase[hh * (NPTS / 2) + cb + off];
        }
        __syncthreads();

        const float4* my = chunk + half * KNN_CH;
        for (int i = 0; i < KNN_CH / 32; i++) {
            float4 p = my[i * 32 + lane];
            // dot: cuBLAS-style FMA chain over k=0,1,2
            float dot = __fmaf_rn(p.z, cz, __fmaf_rn(p.y, cy, __fmul_rn(p.x, cx)));
            // d2 = (c2 + p2) - 2*dot, contracted: fma(-2, dot, c2+p2)
            float d2  = __fmaf_rn(-2.0f, dot, __fadd_rn(c2, p.w));
            if (__any_sync(0xffffffffu, d2 <= curMax)) {
                unsigned int ub = __float_as_uint(d2);
                ub ^= (ub & 0x80000000u) ? 0xFFFFFFFFu : 0x80000000u;   // order-preserving flip
                unsigned int gi = (unsigned int)(hbase + cb + i * 32 + lane);
                unsigned long long cand = ((unsigned long long)ub << 32) | gi;
                cand = bsort32(cand, lane);
                unsigned long long o = __shfl_sync(0xffffffffu, cand, 31 - lane);
                unsigned long long m = (L < o) ? L : o;   // 32 smallest of union (bitonic)
                L = bmerge32(m, lane);
                unsigned long long top = __shfl_sync(0xffffffffu, L, 31);
                unsigned int th = (unsigned int)(top >> 32);
                th ^= (th & 0x80000000u) ? 0x80000000u : 0xFFFFFFFFu;   // un-flip
                curMax = __uint_as_float(th);
            }
        }
    }

    // Merge the two point-halves of each center
    if (half == 1) { smg[cl][lane] = L; }
    __syncthreads();
    if (half == 0) {
        unsigned long long o = smg[cl][31 - lane];
        unsigned long long m = (L < o) ? L : o;
        L = bmerge32(m, lane);
        // lane == rank k: gather + subtract center
        unsigned int gi = (unsigned int)L;
        float4 p = pbase[gi];
        float* dst = patches_out + ((size_t)(b * NPAT + c) * KNN + lane) * 3;
        dst[0] = p.x - cx;
        dst[1] = p.y - cy;
        dst[2] = p.z - cz;
    }
}

// ---------------------------------------------------------------------------
// Launch: prep -> fps -> knn (stream-ordered, graph-capturable, alloc-free)
// Output layout: tuple(patches, centers) flattened: [NB*NPAT*KNN*3] then [NB*NPAT*3]
// ---------------------------------------------------------------------------
extern "C" void kernel_launch(void* const* d_in, const int* in_sizes, int n_in,
                              void* d_out, int out_size) {
    const float* pts = (const float*)d_in[0];
    float* out      = (float*)d_out;
    float* patches  = out;                               // 16*64*32*3 = 98304
    float* centers  = out + (size_t)NB * NPAT * KNN * 3; // 16*64*3   =  3072

    prep_kernel<<<4096, 256>>>(pts);
    fps_kernel<<<dim3(FPS_BLKS, NB), FPS_THR>>>(centers);
    knn_kernel<<<dim3(8, NB), 512>>>(centers, patches);
}

// round 3
// speedup vs baseline: 1.9413x; 1.9413x over previous
#include <cuda_runtime.h>
#include <cuda_bf16.h>
#include <cstdint>

// Problem constants
#define NB   16
#define NPTS 65536
#define NPAT 64      // NUM_PATCHES
#define KNN  32      // PATCH_SIZE

// FPS decomposition: 8 blocks per batch, 1024 threads, 8 points per thread
#define FPS_BLKS   8
#define FPS_THR    1024
#define FPS_PPT    8           // points per thread = NPTS / (FPS_BLKS*FPS_THR)

typedef unsigned long long u64;
typedef unsigned int u32;

// Scratch (allocation-free rule: __device__ globals)
__device__ float4 g_pts4[NB * NPTS];             // x,y,z,|p|^2 (FMA-chain p2)
__device__ u64    g_part[NB * NPAT * FPS_BLKS];  // per-iter per-block argmax slot

// ---- packed f32x2 helpers (separate mul/add => bit-identical to scalar RN) ----
__device__ __forceinline__ u64 pk2(float a, float b) {
    u64 r; asm("mov.b64 %0,{%1,%2};" : "=l"(r) : "f"(a), "f"(b)); return r;
}
__device__ __forceinline__ void upk2(u64 v, float& a, float& b) {
    asm("mov.b64 {%0,%1},%2;" : "=f"(a), "=f"(b) : "l"(v));
}
__device__ __forceinline__ u64 add2(u64 a, u64 b) {
    u64 r; asm("add.rn.f32x2 %0,%1,%2;" : "=l"(r) : "l"(a), "l"(b)); return r;
}
__device__ __forceinline__ u64 mul2(u64 a, u64 b) {
    u64 r; asm("mul.rn.f32x2 %0,%1,%2;" : "=l"(r) : "l"(a), "l"(b)); return r;
}

// ---------------------------------------------------------------------------
// Kernel 0: prep — pad points to float4 with p2 (vectorized), zero FPS slots.
// p2 uses the XLA/LLVM FP-contraction shape: fma(z,z, fma(y,y, x*x))
// ---------------------------------------------------------------------------
__global__ void prep_kernel(const float* __restrict__ pts) {
    int i = blockIdx.x * blockDim.x + threadIdx.x;   // 262144 threads
    if (i < NB * NPAT * FPS_BLKS) g_part[i] = 0ull;
    // each thread: 4 points via 3 float4 loads
    const float4* in4 = (const float4*)pts;
    float4 a = in4[3 * i + 0];
    float4 b = in4[3 * i + 1];
    float4 c = in4[3 * i + 2];
    float xs[4] = {a.x, a.w, b.z, c.y};
    float ys[4] = {a.y, b.x, b.w, c.z};
    float zs[4] = {a.z, b.y, c.x, c.w};
#pragma unroll
    for (int j = 0; j < 4; j++) {
        float p2 = __fmaf_rn(zs[j], zs[j], __fmaf_rn(ys[j], ys[j], __fmul_rn(xs[j], xs[j])));
        g_pts4[4 * i + j] = make_float4(xs[j], ys[j], zs[j], p2);
    }
}

// ---------------------------------------------------------------------------
// Kernel 1: FPS — 8 cooperating blocks per batch. Points (packed f32x2) and
// min_d in registers. Per-iteration all-to-all via L2 slots: every block's
// warp-0 lanes 0-7 poll the 8 slots IN PARALLEL, reduce, and fetch winner
// coords themselves (no broadcast hop). Arithmetic bit-identical to round 2.
// ---------------------------------------------------------------------------
__global__ void __launch_bounds__(FPS_THR, 1)
fps_kernel(float* __restrict__ centers_out /* [NB][NPAT][3] */) {
    const int b    = blockIdx.y;
    const int sub  = blockIdx.x;          // 0..7
    const int tid  = threadIdx.x;
    const int lane = tid & 31;
    const int wid  = tid >> 5;            // 0..31

    const float4* pts = g_pts4 + (size_t)b * NPTS;
    const int gbase = sub * (NPTS / FPS_BLKS);   // 8192 per sub-block

    // 8 points per thread, stored as 4 packed pairs (lo: gi0, hi: gi0+1024)
    u64 pxk[4], pyk[4], pzk[4];
    float md[8];
#pragma unroll
    for (int jj = 0; jj < 4; jj++) {
        float4 p0 = pts[gbase + (2 * jj) * FPS_THR + tid];
        float4 p1 = pts[gbase + (2 * jj + 1) * FPS_THR + tid];
        pxk[jj] = pk2(p0.x, p1.x);
        pyk[jj] = pk2(p0.y, p1.y);
        pzk[jj] = pk2(p0.z, p1.z);
        md[2 * jj] = 3.402823466e38f;
        md[2 * jj + 1] = 3.402823466e38f;
    }

    __shared__ float sc[4];
    __shared__ u64 wb[32];

    volatile u64* part = (volatile u64*)(g_part + (size_t)b * NPAT * FPS_BLKS);

    // initial center = point 0
    if (tid == 0) {
        float4 c = pts[0];
        sc[0] = c.x; sc[1] = c.y; sc[2] = c.z;
    }

    for (int iter = 0; iter < NPAT; iter++) {
        __syncthreads();   // sc valid
        float cx = sc[0], cy = sc[1], cz = sc[2];
        if (sub == 0 && tid == 0) {
            centers_out[(b * NPAT + iter) * 3 + 0] = cx;
            centers_out[(b * NPAT + iter) * 3 + 1] = cy;
            centers_out[(b * NPAT + iter) * 3 + 2] = cz;
        }
        if (iter == NPAT - 1) break;   // last winner never used

        // packed -c
        u64 ncx = pk2(-cx, -cx), ncy = pk2(-cy, -cy), ncz = pk2(-cz, -cz);

        float bestv = -1.0f;
        u32   besti = 0;
#pragma unroll
        for (int jj = 0; jj < 4; jj++) {
            // dx = px + (-cx) == px - cx bitwise; d = ((dx*dx + dy*dy) + dz*dz)
            u64 dx = add2(pxk[jj], ncx);
            u64 dy = add2(pyk[jj], ncy);
            u64 dz = add2(pzk[jj], ncz);
            u64 s  = add2(add2(mul2(dx, dx), mul2(dy, dy)), mul2(dz, dz));
            float d0, d1; upk2(s, d0, d1);
            u32 gi0 = (u32)(gbase + (2 * jj) * FPS_THR + tid);
            float m0 = fminf(md[2 * jj], d0);     md[2 * jj] = m0;
            if (m0 > bestv) { bestv = m0; besti = gi0; }
            float m1 = fminf(md[2 * jj + 1], d1); md[2 * jj + 1] = m1;
            if (m1 > bestv) { bestv = m1; besti = gi0 + FPS_THR; }
        }
        // key: ties -> lowest index (jnp.argmax picks first)
        u64 best = ((u64)__float_as_uint(bestv) << 32) | (u32)(~besti);
#pragma unroll
        for (int off = 16; off; off >>= 1) {
            u64 o = __shfl_xor_sync(0xffffffffu, best, off);
            if (o > best) best = o;
        }
        if (lane == 0) wb[wid] = best;
        __syncthreads();
        if (wid == 0) {
            u64 v = wb[lane];
#pragma unroll
            for (int off = 16; off; off >>= 1) {
                u64 o = __shfl_xor_sync(0xffffffffu, v, off);
                if (o > v) v = o;
            }
            // publish this block's partial
            if (lane == 0) part[iter * FPS_BLKS + sub] = v;
            // parallel poll: lanes 0-7 each watch one slot
            u64 s = 0ull;
            if (lane < FPS_BLKS) {
                volatile u64* sl = &part[iter * FPS_BLKS + lane];
                while ((s = *sl) == 0ull) { __nanosleep(20); }
            }
#pragma unroll
            for (int off = 4; off; off >>= 1) {
                u64 o = __shfl_xor_sync(0xffffffffu, s, off);
                if (o > s) s = o;
            }
            if (lane == 0) {
                u32 wi = ~(u32)s;          // winning global index
                float4 c = pts[wi];
                sc[0] = c.x; sc[1] = c.y; sc[2] = c.z;
            }
        }
    }
}

// ---------------------------------------------------------------------------
// Kernel 2: exact KNN top-32. 1024 threads = 32 warps = 8 centers x 4
// point-quarters. Steady state: scalar gate (~10 inst / 32 pts). Accepts via
// O(1) sorted insertion (u64 keys, exact); bitonic fallback when popc > 8.
// ---------------------------------------------------------------------------
__device__ __forceinline__ u64 bsort32(u64 v, int lane) {
#pragma unroll
    for (int k = 2; k <= 32; k <<= 1) {
#pragma unroll
        for (int j = k >> 1; j > 0; j >>= 1) {
            u64 o = __shfl_xor_sync(0xffffffffu, v, j);
            bool up      = ((lane & k) == 0);
            bool keepmin = (((lane & j) == 0) == up);
            bool smaller = (v < o);
            v = (smaller == keepmin) ? v : o;
        }
    }
    return v;
}
__device__ __forceinline__ u64 bmerge32(u64 v, int lane) {
#pragma unroll
    for (int j = 16; j > 0; j >>= 1) {
        u64 o = __shfl_xor_sync(0xffffffffu, v, j);
        bool keepmin = ((lane & j) == 0);
        bool smaller = (v < o);
        v = (smaller == keepmin) ? v : o;
    }
    return v;
}
__device__ __forceinline__ u32 flipf(float f) {
    u32 u = __float_as_uint(f);
    return u ^ ((u & 0x80000000u) ? 0xFFFFFFFFu : 0x80000000u);
}

#define KNN_CH 512           // points per quarter per chunk
#define QTR    (NPTS / 4)    // 16384

__global__ void __launch_bounds__(1024, 1)
knn_kernel(const float* __restrict__ centers /* [NB][NPAT][3] */,
           float* __restrict__ patches_out   /* [NB][NPAT][KNN][3] */) {
    const int b    = blockIdx.y;      // 16
    const int grp  = blockIdx.x;      // 8 -> centers grp*8 .. grp*8+7
    const int tid  = threadIdx.x;
    const int lane = tid & 31;
    const int w    = tid >> 5;        // 0..31
    const int cl   = w & 7;           // center within group
    const int q    = w >> 3;          // quarter 0..3
    const int c    = grp * 8 + cl;

    const float4* pbase = g_pts4 + (size_t)b * NPTS;

    const float cx = centers[(b * NPAT + c) * 3 + 0];
    const float cy = centers[(b * NPAT + c) * 3 + 1];
    const float cz = centers[(b * NPAT + c) * 3 + 2];
    const float c2 = __fmaf_rn(cz, cz, __fmaf_rn(cy, cy, __fmul_rn(cx, cx)));

    u64 L = 0xFF80000000000000ull;              // key for d2=+inf, idx 0
    float curMax = __int_as_float(0x7f800000);  // +inf

    __shared__ float4 chunk[4 * KNN_CH];        // 32 KB
    __shared__ u64 smg[8][3][32];               // 6 KB quarter-merge buffers

    const int qbase = q * QTR;

    for (int cb = 0; cb < QTR; cb += KNN_CH) {
        __syncthreads();
        for (int t = tid; t < 4 * KNN_CH; t += 1024) {
            int qq = t >> 9;
            int off = t & (KNN_CH - 1);
            chunk[t] = pbase[qq * QTR + cb + off];
        }
        __syncthreads();

        const float4* my = chunk + q * KNN_CH;
        float4 p = my[lane];
        for (int i = 0; i < KNN_CH / 32; i++) {
            float4 pn;
            if (i < KNN_CH / 32 - 1) pn = my[(i + 1) * 32 + lane];
            // XLA-shape d2: fma(-2, dot, c2+p2), dot = fma chain
            float dot = __fmaf_rn(p.z, cz, __fmaf_rn(p.y, cy, __fmul_rn(p.x, cx)));
            float d2  = __fmaf_rn(-2.0f, dot, __fadd_rn(c2, p.w));
            u32 mask = __ballot_sync(0xffffffffu, d2 <= curMax);
            if (mask) {
                u32 gi = (u32)(qbase + cb + i * 32 + lane);
                u64 cand = ((u64)flipf(d2) << 32) | gi;
                if (__popc(mask) <= 8) {
                    while (mask) {
                        int src = __ffs(mask) - 1; mask &= mask - 1;
                        u64 k  = __shfl_sync(0xffffffffu, cand, src);
                        u64 up = __shfl_up_sync(0xffffffffu, L, 1);
                        if (lane == 0) up = k;
                        u64 mx = (k > up) ? k : up;
                        L = (L < k) ? L : mx;
                    }
                } else {
                    u64 cs = bsort32(cand, lane);
                    u64 o  = __shfl_sync(0xffffffffu, cs, 31 - lane);
                    u64 m  = (L < o) ? L : o;
                    L = bmerge32(m, lane);
                }
                u64 top = __shfl_sync(0xffffffffu, L, 31);
                u32 th = (u32)(top >> 32);
                th ^= (th & 0x80000000u) ? 0x80000000u : 0xFFFFFFFFu;
                curMax = __uint_as_float(th);
            }
            p = pn;
        }
    }

    // merge 4 quarters per center: (1->0, 3->2), then (2->0)
    if (q == 1) { smg[cl][0][lane] = L; }
    if (q == 3) { smg[cl][1][lane] = L; }
    __syncthreads();
    if (q == 0) { u64 o = smg[cl][0][31 - lane]; u64 m = (L < o) ? L : o; L = bmerge32(m, lane); }
    if (q == 2) { u64 o = smg[cl][1][31 - lane]; u64 m = (L < o) ? L : o; L = bmerge32(m, lane); }
    __syncthreads();
    if (q == 2) { smg[cl][2][lane] = L; }
    __syncthreads();
    if (q == 0) {
        u64 o = smg[cl][2][31 - lane]; u64 m = (L < o) ? L : o; L = bmerge32(m, lane);
        // lane == rank k: gather + subtract center
        u32 gi = (u32)L;
        float4 p = pbase[gi];
        float* dst = patches_out + ((size_t)(b * NPAT + c) * KNN + lane) * 3;
        dst[0] = p.x - cx;
        dst[1] = p.y - cy;
        dst[2] = p.z - cz;
    }
}

// ---------------------------------------------------------------------------
// Launch: prep -> fps -> knn (stream-ordered, graph-capturable, alloc-free)
// Output: tuple(patches, centers): [NB*NPAT*KNN*3] then [NB*NPAT*3]
// ---------------------------------------------------------------------------
extern "C" void kernel_launch(void* const* d_in, const int* in_sizes, int n_in,
                              void* d_out, int out_size) {
    const float* pts = (const float*)d_in[0];
    float* out      = (float*)d_out;
    float* patches  = out;                               // 16*64*32*3 = 98304
    float* centers  = out + (size_t)NB * NPAT * KNN * 3; // 16*64*3   =  3072

    prep_kernel<<<1024, 256>>>(pts);                     // 262144 threads = NB*NPTS/4
    fps_kernel<<<dim3(FPS_BLKS, NB), FPS_THR>>>(centers);
    knn_kernel<<<dim3(8, NB), 1024>>>(centers, patches);
}